// round 11
// baseline (speedup 1.0000x reference)
#include <cuda_runtime.h>
#include <cuda_fp16.h>
#include <cstdint>

#define NB    256
#define NNEG  1024
#define DD    256
#define DD2   512
#define BM    64                     // tails per CTA (halved for 2 CTA/SM)
#define BK    32                     // fp16 k per chunk
#define NCH   8
#define RPAD  40                     // fp16 per padded row (80B, stride 20 banks)
#define A_STAGE_B (BM  * RPAD * 2)   // 5120
#define B_STAGE_B (DD  * RPAD * 2)   // 20480
#define STAGE_B   (A_STAGE_B + B_STAGE_B)  // 25600
#define SMEM_MAIN (4 * STAGE_B)            // 102400

__device__ float  g_hn[NB * DD];
__device__ float  g_rp[NB * DD];
__device__ __half g_Wh[DD * DD];     // entity half of W, fp16, [n][k]
__device__ float  g_Wtf[DD2 * DD];   // W transposed fp32: [k][j]

#define CP16(d, s) asm volatile("cp.async.cg.shared.global [%0], [%1], 16;" :: "r"(d), "l"(s) : "memory")
#define LDSM4(r0, r1, r2, r3, a) asm volatile( \
    "ldmatrix.sync.aligned.m8n8.x4.shared.b16 {%0,%1,%2,%3}, [%4];" \
    : "=r"(r0), "=r"(r1), "=r"(r2), "=r"(r3) : "r"(a))

__device__ __forceinline__ uint32_t smem_u32(const void* p) {
    uint32_t a;
    asm("{ .reg .u64 t; cvta.to.shared.u64 t, %1; cvt.u32.u64 %0, t; }" : "=r"(a) : "l"(p));
    return a;
}
__device__ __forceinline__ uint32_t h2_bits(__half2 h) {
    return *reinterpret_cast<uint32_t*>(&h);
}
__device__ __forceinline__ void mma16(float* c, const uint32_t* a, uint32_t b0, uint32_t b1) {
    asm volatile(
        "mma.sync.aligned.m16n8k16.row.col.f32.f16.f16.f32 "
        "{%0,%1,%2,%3}, {%4,%5,%6,%7}, {%8,%9}, {%0,%1,%2,%3};"
        : "+f"(c[0]), "+f"(c[1]), "+f"(c[2]), "+f"(c[3])
        : "r"(a[0]), "r"(a[1]), "r"(a[2]), "r"(a[3]), "r"(b0), "r"(b1));
}

// ---------------------------------------------------------------------------
// Kernel 0: tiled transpose of W (fp32 [k][j]) + fp16 copy of entity half
// ---------------------------------------------------------------------------
__global__ void k_transW(const float* __restrict__ W) {
    __shared__ float t[32][33];
    int tx = threadIdx.x, ty = threadIdx.y;
    int j0 = blockIdx.y * 32;
    int k0 = blockIdx.x * 32;
    float v = W[(j0 + ty) * DD2 + k0 + tx];
    t[ty][tx] = v;
    if (k0 + tx < DD)
        g_Wh[(j0 + ty) * DD + k0 + tx] = __float2half_rn(v);
    __syncthreads();
    g_Wtf[(k0 + ty) * DD + (j0 + tx)] = t[tx][ty];
}

// ---------------------------------------------------------------------------
// Kernel 1: batched head FC + rel-tail projection (shuffle-free, coalesced)
// ---------------------------------------------------------------------------
__global__ void __launch_bounds__(256, 1) k_prep(
    const int* __restrict__ head, const int* __restrict__ rel,
    const float* __restrict__ ent, const float* __restrict__ remb,
    const float* __restrict__ bfc)
{
    __shared__ float hc[4][DD2];
    __shared__ float rt[4][DD];
    __shared__ float hf[4][DD];
    __shared__ float inv_s[4];

    int tid = threadIdx.x;
    int b0 = blockIdx.x * 4;

    for (int i = tid; i < 4 * DD2; i += 256) {
        int bb = i >> 9, k = i & 511;
        int b = b0 + bb;
        hc[bb][k] = (k < DD) ? ent[(long)head[b] * DD + k]
                             : remb[(long)rel[b] * DD2 + (k - DD)];
    }
    for (int i = tid; i < 4 * DD; i += 256) {
        int bb = i >> 8, k = i & 255;
        rt[bb][k] = remb[(long)rel[b0 + bb] * DD2 + DD + k];
    }
    __syncthreads();

    int j = tid;
    float aH[4] = {0.f, 0.f, 0.f, 0.f}, aT[4] = {0.f, 0.f, 0.f, 0.f};
    const float* wt = g_Wtf + j;
    #pragma unroll 4
    for (int k = 0; k < DD; k++) {
        float w = wt[(long)k * DD];
        #pragma unroll
        for (int bb = 0; bb < 4; bb++) aH[bb] += w * hc[bb][k];
    }
    #pragma unroll 4
    for (int k = DD; k < DD2; k++) {
        float w = wt[(long)k * DD];
        #pragma unroll
        for (int bb = 0; bb < 4; bb++) {
            aH[bb] += w * hc[bb][k];
            aT[bb] += w * rt[bb][k - DD];
        }
    }
    float bj = bfc[j];
    #pragma unroll
    for (int bb = 0; bb < 4; bb++) {
        hf[bb][j] = aH[bb] + bj;
        g_rp[(b0 + bb) * DD + j] = aT[bb] + bj;
    }
    __syncthreads();

    int wid = tid >> 5, lane = tid & 31;
    if (wid < 4) {
        float s = 0.f;
        #pragma unroll
        for (int q = lane; q < DD; q += 32) { float v = hf[wid][q]; s += v * v; }
        #pragma unroll
        for (int o = 16; o; o >>= 1) s += __shfl_xor_sync(0xffffffffu, s, o);
        if (lane == 0) inv_s[wid] = 1.0f / fmaxf(sqrtf(s), 1e-12f);
    }
    __syncthreads();
    #pragma unroll
    for (int bb = 0; bb < 4; bb++)
        g_hn[(b0 + bb) * DD + j] = hf[bb][j] * inv_s[bb];
}

// ---------------------------------------------------------------------------
// Kernel 2: fp16 mma.sync + ldmatrix gathered GEMM
//   256 threads / 8 warps (2m x 4n), CTA tile 64x256, 2 CTAs/SM.
// ---------------------------------------------------------------------------
__global__ void __launch_bounds__(256, 2) k_main(
    const int* __restrict__ tail, const float* __restrict__ ent,
    float* __restrict__ out)
{
    extern __shared__ char smc[];
    __shared__ int   tidx[BM];
    __shared__ float rp_s[DD], hn_s[DD];
    __shared__ float sqp[BM][4];
    __shared__ float spp[BM][4];
    __shared__ float invb[BM];

    int tid = threadIdx.x, lane = tid & 31, wid = tid >> 5;
    int b = blockIdx.y, tile0 = blockIdx.x * BM;
    int wm = wid >> 2, wn = wid & 3;           // 2 x 4 warp grid
    int lg = lane >> 2, lt = lane & 3;

    if (tid < BM) tidx[tid] = tail[b * NNEG + tile0 + tid];
    rp_s[tid] = g_rp[b * DD + tid];
    hn_s[tid] = g_hn[b * DD + tid];
    __syncthreads();

    uint32_t sb = smem_u32(smc);

    // A producer: 4 threads/row over 64 rows; seg = 8 floats -> 8 halves (16B)
    int arow = tid >> 2, aseg = tid & 3;
    const float* aSrc = ent + (long)tidx[arow] * DD + aseg * 8;
    uint32_t aOff = (uint32_t)(arow * (RPAD * 2) + aseg * 16);

    // B producer: 1 thread/row over 256 rows; 32 halves = 4 x 16B cp.async
    int brow = tid;
    const __half* bSrc = g_Wh + (long)brow * DD;
    uint32_t bDst = sb + (uint32_t)(A_STAGE_B + brow * (RPAD * 2));

    uint32_t aLm[2], bLm[4];
    #pragma unroll
    for (int i = 0; i < 2; i++) {
        int row = wm * 32 + i * 16 + (lane & 7) + ((lane >> 3) & 1) * 8;
        int kc  = ((lane >> 4) & 1) * 8;
        aLm[i] = sb + (uint32_t)(row * (RPAD * 2) + kc * 2);
    }
    #pragma unroll
    for (int p = 0; p < 4; p++) {
        int rn = wn * 64 + p * 16 + (lane & 7) + ((lane >> 4) & 1) * 8;
        int kc = ((lane >> 3) & 1) * 8;
        bLm[p] = sb + (uint32_t)(A_STAGE_B + rn * (RPAD * 2) + kc * 2);
    }

    float4 regA[2][2];
    #define LDGA(c, buf) do {                                   \
        regA[buf][0] = *(const float4*)(aSrc + (c) * BK);       \
        regA[buf][1] = *(const float4*)(aSrc + (c) * BK + 4);   \
    } while (0)
    #define STSA(c, buf) do {                                   \
        __half2 h0 = __floats2half2_rn(regA[buf][0].x, regA[buf][0].y); \
        __half2 h1 = __floats2half2_rn(regA[buf][0].z, regA[buf][0].w); \
        __half2 h2 = __floats2half2_rn(regA[buf][1].x, regA[buf][1].y); \
        __half2 h3 = __floats2half2_rn(regA[buf][1].z, regA[buf][1].w); \
        uint4 u;                                                \
        u.x = h2_bits(h0); u.y = h2_bits(h1);                   \
        u.z = h2_bits(h2); u.w = h2_bits(h3);                   \
        *(uint4*)(smc + (((c) & 3) * STAGE_B) + aOff) = u;      \
    } while (0)
    #define CPB(c) do {                                                   \
        uint32_t _d = bDst + ((c) & 3) * STAGE_B;                         \
        const __half* _s = bSrc + (c) * BK;                               \
        CP16(_d,      _s);                                                \
        CP16(_d + 16, _s + 8);                                            \
        CP16(_d + 32, _s + 16);                                           \
        CP16(_d + 48, _s + 24);                                           \
        asm volatile("cp.async.commit_group;" ::: "memory");              \
    } while (0)

    float acc[2][8][4];
    #pragma unroll
    for (int i = 0; i < 2; i++)
        #pragma unroll
        for (int t = 0; t < 8; t++)
            #pragma unroll
            for (int q = 0; q < 4; q++) acc[i][t][q] = 0.f;

    LDGA(0, 0); CPB(0);
    LDGA(1, 1); CPB(1);

    #pragma unroll
    for (int c = 0; c < NCH; c++) {
        if (c < NCH - 1) asm volatile("cp.async.wait_group 1;" ::: "memory");
        else             asm volatile("cp.async.wait_group 0;" ::: "memory");
        STSA(c, c & 1);
        __syncthreads();
        if (c + 2 < NCH) { LDGA(c + 2, c & 1); CPB(c + 2); }

        uint32_t stOff = (uint32_t)((c & 3) * STAGE_B);

        #pragma unroll
        for (int ks = 0; ks < 2; ks++) {
            uint32_t ko = stOff + ks * 32u;
            uint32_t a[2][4];
            LDSM4(a[0][0], a[0][1], a[0][2], a[0][3], aLm[0] + ko);
            LDSM4(a[1][0], a[1][1], a[1][2], a[1][3], aLm[1] + ko);
            uint32_t bf[4][4];
            #pragma unroll
            for (int p = 0; p < 4; p++)
                LDSM4(bf[p][0], bf[p][1], bf[p][2], bf[p][3], bLm[p] + ko);
            #pragma unroll
            for (int t = 0; t < 8; t++) {
                uint32_t b0 = bf[t >> 1][(t & 1) * 2 + 0];
                uint32_t b1 = bf[t >> 1][(t & 1) * 2 + 1];
                #pragma unroll
                for (int i = 0; i < 2; i++) mma16(acc[i][t], a[i], b0, b1);
            }
        }
    }
    #undef LDGA
    #undef STSA
    #undef CPB

    // ---- epilogue ----
    #pragma unroll
    for (int i = 0; i < 2; i++) {
        #pragma unroll
        for (int rh = 0; rh < 2; rh++) {
            float s = 0.f;
            #pragma unroll
            for (int t = 0; t < 8; t++) {
                int n0 = wn * 64 + t * 8 + 2 * lt;
                float c0 = acc[i][t][rh * 2 + 0] + rp_s[n0];
                float c1 = acc[i][t][rh * 2 + 1] + rp_s[n0 + 1];
                s += c0 * c0 + c1 * c1;
            }
            s += __shfl_xor_sync(0xffffffffu, s, 1);
            s += __shfl_xor_sync(0xffffffffu, s, 2);
            if (lt == 0) sqp[wm * 32 + i * 16 + rh * 8 + lg][wn] = s;
        }
    }
    __syncthreads();
    if (tid < BM) {
        float sq = sqp[tid][0] + sqp[tid][1] + sqp[tid][2] + sqp[tid][3];
        invb[tid] = 1.0f / fmaxf(sqrtf(sq), 1e-12f);
    }
    __syncthreads();

    #pragma unroll
    for (int i = 0; i < 2; i++) {
        #pragma unroll
        for (int rh = 0; rh < 2; rh++) {
            int row = wm * 32 + i * 16 + rh * 8 + lg;
            float inv = invb[row];
            float s = 0.f;
            #pragma unroll
            for (int t = 0; t < 8; t++) {
                int n0 = wn * 64 + t * 8 + 2 * lt;
                float t0 = (acc[i][t][rh * 2 + 0] + rp_s[n0])     * inv;
                float t1 = (acc[i][t][rh * 2 + 1] + rp_s[n0 + 1]) * inv;
                s += fabsf(hn_s[n0] - t0) + fabsf(hn_s[n0 + 1] - t1);
            }
            s += __shfl_xor_sync(0xffffffffu, s, 1);
            s += __shfl_xor_sync(0xffffffffu, s, 2);
            if (lt == 0) spp[row][wn] = s;
        }
    }
    __syncthreads();
    if (tid < BM)
        out[b * NNEG + tile0 + tid] =
            12.0f - (spp[tid][0] + spp[tid][1] + spp[tid][2] + spp[tid][3]);
}

// ---------------------------------------------------------------------------
extern "C" void kernel_launch(void* const* d_in, const int* in_sizes, int n_in,
                              void* d_out, int out_size)
{
    const int*   head = (const int*)  d_in[0];
    const int*   tail = (const int*)  d_in[1];
    const int*   rel  = (const int*)  d_in[2];
    const float* ent  = (const float*)d_in[3];
    const float* remb = (const float*)d_in[4];
    const float* W    = (const float*)d_in[5];
    const float* bfc  = (const float*)d_in[6];
    float* out = (float*)d_out;

    cudaFuncSetAttribute(k_main, cudaFuncAttributeMaxDynamicSharedMemorySize, SMEM_MAIN);

    k_transW<<<dim3(16, 8), dim3(32, 32)>>>(W);
    k_prep<<<NB / 4, 256>>>(head, rel, ent, remb, bfc);
    k_main<<<dim3(NNEG / BM, NB), 256, SMEM_MAIN>>>(tail, ent, out);
}

// round 12
// speedup vs baseline: 1.3265x; 1.3265x over previous
#include <cuda_runtime.h>
#include <cuda_fp16.h>
#include <cstdint>

#define NB    256
#define NNEG  1024
#define DD    256
#define DD2   512
#define BM    128
#define BK    32                     // fp16 k per chunk
#define NCH   8
#define RPAD  40                     // fp16 per padded row (80B, stride 20 banks)
#define A_STAGE_B (BM  * RPAD * 2)   // 10240
#define B_STAGE_B (DD  * RPAD * 2)   // 20480
#define STAGE_B   (A_STAGE_B + B_STAGE_B)  // 30720
#define SMEM_MAIN (4 * STAGE_B)            // 122880

__device__ float  g_hn[NB * DD];
__device__ float  g_rp[NB * DD];
__device__ __half g_Wh[DD * DD];     // entity half of W, fp16, [n][k]
__device__ float  g_Wtf[DD2 * DD];   // W transposed fp32: [k][j]

#define CP16(d, s) asm volatile("cp.async.cg.shared.global [%0], [%1], 16;" :: "r"(d), "l"(s) : "memory")
#define LDSM4(r0, r1, r2, r3, a) asm volatile( \
    "ldmatrix.sync.aligned.m8n8.x4.shared.b16 {%0,%1,%2,%3}, [%4];" \
    : "=r"(r0), "=r"(r1), "=r"(r2), "=r"(r3) : "r"(a))

__device__ __forceinline__ uint32_t smem_u32(const void* p) {
    uint32_t a;
    asm("{ .reg .u64 t; cvta.to.shared.u64 t, %1; cvt.u32.u64 %0, t; }" : "=r"(a) : "l"(p));
    return a;
}
__device__ __forceinline__ uint32_t h2_bits(__half2 h) {
    return *reinterpret_cast<uint32_t*>(&h);
}
__device__ __forceinline__ void mma16(float* c, const uint32_t* a, uint32_t b0, uint32_t b1) {
    asm volatile(
        "mma.sync.aligned.m16n8k16.row.col.f32.f16.f16.f32 "
        "{%0,%1,%2,%3}, {%4,%5,%6,%7}, {%8,%9}, {%0,%1,%2,%3};"
        : "+f"(c[0]), "+f"(c[1]), "+f"(c[2]), "+f"(c[3])
        : "r"(a[0]), "r"(a[1]), "r"(a[2]), "r"(a[3]), "r"(b0), "r"(b1));
}

// ---------------------------------------------------------------------------
// Kernel 0: tiled transpose of W (fp32 [k][j]) + fp16 copy of entity half
// ---------------------------------------------------------------------------
__global__ void k_transW(const float* __restrict__ W) {
    __shared__ float t[32][33];
    int tx = threadIdx.x, ty = threadIdx.y;
    int j0 = blockIdx.y * 32;
    int k0 = blockIdx.x * 32;
    float v = W[(j0 + ty) * DD2 + k0 + tx];
    t[ty][tx] = v;
    if (k0 + tx < DD)
        g_Wh[(j0 + ty) * DD + k0 + tx] = __float2half_rn(v);
    __syncthreads();
    g_Wtf[(k0 + ty) * DD + (j0 + tx)] = t[tx][ty];
}

// ---------------------------------------------------------------------------
// Kernel 1: batched head FC + rel-tail projection (shuffle-free, coalesced)
// ---------------------------------------------------------------------------
__global__ void __launch_bounds__(256, 1) k_prep(
    const int* __restrict__ head, const int* __restrict__ rel,
    const float* __restrict__ ent, const float* __restrict__ remb,
    const float* __restrict__ bfc)
{
    __shared__ float hc[4][DD2];
    __shared__ float rt[4][DD];
    __shared__ float hf[4][DD];
    __shared__ float inv_s[4];

    int tid = threadIdx.x;
    int b0 = blockIdx.x * 4;

    for (int i = tid; i < 4 * DD2; i += 256) {
        int bb = i >> 9, k = i & 511;
        int b = b0 + bb;
        hc[bb][k] = (k < DD) ? ent[(long)head[b] * DD + k]
                             : remb[(long)rel[b] * DD2 + (k - DD)];
    }
    for (int i = tid; i < 4 * DD; i += 256) {
        int bb = i >> 8, k = i & 255;
        rt[bb][k] = remb[(long)rel[b0 + bb] * DD2 + DD + k];
    }
    __syncthreads();

    int j = tid;
    float aH[4] = {0.f, 0.f, 0.f, 0.f}, aT[4] = {0.f, 0.f, 0.f, 0.f};
    const float* wt = g_Wtf + j;
    #pragma unroll 4
    for (int k = 0; k < DD; k++) {
        float w = wt[(long)k * DD];
        #pragma unroll
        for (int bb = 0; bb < 4; bb++) aH[bb] += w * hc[bb][k];
    }
    #pragma unroll 4
    for (int k = DD; k < DD2; k++) {
        float w = wt[(long)k * DD];
        #pragma unroll
        for (int bb = 0; bb < 4; bb++) {
            aH[bb] += w * hc[bb][k];
            aT[bb] += w * rt[bb][k - DD];
        }
    }
    float bj = bfc[j];
    #pragma unroll
    for (int bb = 0; bb < 4; bb++) {
        hf[bb][j] = aH[bb] + bj;
        g_rp[(b0 + bb) * DD + j] = aT[bb] + bj;
    }
    __syncthreads();

    int wid = tid >> 5, lane = tid & 31;
    if (wid < 4) {
        float s = 0.f;
        #pragma unroll
        for (int q = lane; q < DD; q += 32) { float v = hf[wid][q]; s += v * v; }
        #pragma unroll
        for (int o = 16; o; o >>= 1) s += __shfl_xor_sync(0xffffffffu, s, o);
        if (lane == 0) inv_s[wid] = 1.0f / fmaxf(sqrtf(s), 1e-12f);
    }
    __syncthreads();
    #pragma unroll
    for (int bb = 0; bb < 4; bb++)
        g_hn[(b0 + bb) * DD + j] = hf[bb][j] * inv_s[bb];
}

// ---------------------------------------------------------------------------
// Kernel 2: fp16 mma.sync + ldmatrix gathered GEMM (R10 config; chunk-wide
// fragment batch: all 12 LDSM issued before the 32 MMAs of a chunk)
// ---------------------------------------------------------------------------
__global__ void __launch_bounds__(512, 1) k_main(
    const int* __restrict__ tail, const float* __restrict__ ent,
    float* __restrict__ out)
{
    extern __shared__ char smc[];
    __shared__ int   tidx[BM];
    __shared__ float rp_s[DD], hn_s[DD];
    __shared__ float sqp[BM][4];
    __shared__ float spp[BM][4];
    __shared__ float invb[BM];

    int tid = threadIdx.x, lane = tid & 31, wid = tid >> 5;
    int b = blockIdx.y, tile0 = blockIdx.x * BM;
    int wm = wid >> 2, wn = wid & 3;
    int lg = lane >> 2, lt = lane & 3;

    if (tid < BM) tidx[tid] = tail[b * NNEG + tile0 + tid];
    if (tid < DD) { rp_s[tid] = g_rp[b * DD + tid]; hn_s[tid] = g_hn[b * DD + tid]; }
    __syncthreads();

    uint32_t sb = smem_u32(smc);

    int arow = tid >> 2, aseg = tid & 3;
    const float* aSrc = ent + (long)tidx[arow] * DD + aseg * 8;
    uint32_t aOff = (uint32_t)(arow * (RPAD * 2) + aseg * 16);

    int brow = tid >> 1, bs0 = tid & 1, bs1 = bs0 + 2;
    const __half* bSrc = g_Wh + (long)brow * DD;
    uint32_t bDst = sb + (uint32_t)(A_STAGE_B + brow * (RPAD * 2));

    uint32_t aLm[2], bLm[4];
    #pragma unroll
    for (int i = 0; i < 2; i++) {
        int row = wm * 32 + i * 16 + (lane & 7) + ((lane >> 3) & 1) * 8;
        int kc  = ((lane >> 4) & 1) * 8;
        aLm[i] = sb + (uint32_t)(row * (RPAD * 2) + kc * 2);
    }
    #pragma unroll
    for (int p = 0; p < 4; p++) {
        int rn = wn * 64 + p * 16 + (lane & 7) + ((lane >> 4) & 1) * 8;
        int kc = ((lane >> 3) & 1) * 8;
        bLm[p] = sb + (uint32_t)(A_STAGE_B + rn * (RPAD * 2) + kc * 2);
    }

    float4 regA[2][2];
    #define LDGA(c, buf) do {                                   \
        regA[buf][0] = *(const float4*)(aSrc + (c) * BK);       \
        regA[buf][1] = *(const float4*)(aSrc + (c) * BK + 4);   \
    } while (0)
    #define STSA(c, buf) do {                                   \
        __half2 h0 = __floats2half2_rn(regA[buf][0].x, regA[buf][0].y); \
        __half2 h1 = __floats2half2_rn(regA[buf][0].z, regA[buf][0].w); \
        __half2 h2 = __floats2half2_rn(regA[buf][1].x, regA[buf][1].y); \
        __half2 h3 = __floats2half2_rn(regA[buf][1].z, regA[buf][1].w); \
        uint4 u;                                                \
        u.x = h2_bits(h0); u.y = h2_bits(h1);                   \
        u.z = h2_bits(h2); u.w = h2_bits(h3);                   \
        *(uint4*)(smc + (((c) & 3) * STAGE_B) + aOff) = u;      \
    } while (0)
    #define CPB(c) do {                                                   \
        uint32_t _d = bDst + ((c) & 3) * STAGE_B;                         \
        CP16(_d + bs0 * 16, bSrc + (c) * BK + bs0 * 8);                   \
        CP16(_d + bs1 * 16, bSrc + (c) * BK + bs1 * 8);                   \
        asm volatile("cp.async.commit_group;" ::: "memory");              \
    } while (0)

    float acc[2][8][4];
    #pragma unroll
    for (int i = 0; i < 2; i++)
        #pragma unroll
        for (int t = 0; t < 8; t++)
            #pragma unroll
            for (int q = 0; q < 4; q++) acc[i][t][q] = 0.f;

    LDGA(0, 0); CPB(0);
    LDGA(1, 1); CPB(1);

    #pragma unroll
    for (int c = 0; c < NCH; c++) {
        if (c < NCH - 1) asm volatile("cp.async.wait_group 1;" ::: "memory");
        else             asm volatile("cp.async.wait_group 0;" ::: "memory");
        STSA(c, c & 1);
        __syncthreads();
        if (c + 2 < NCH) { LDGA(c + 2, c & 1); CPB(c + 2); }

        uint32_t stOff = (uint32_t)((c & 3) * STAGE_B);

        // --- load ALL fragments of this chunk (12 LDSM) up front ---
        uint32_t a[2][2][4];     // [ks][i][frag]
        uint32_t bf[2][4][4];    // [ks][p][frag]
        #pragma unroll
        for (int ks = 0; ks < 2; ks++) {
            uint32_t ko = stOff + ks * 32u;
            LDSM4(a[ks][0][0], a[ks][0][1], a[ks][0][2], a[ks][0][3], aLm[0] + ko);
            LDSM4(a[ks][1][0], a[ks][1][1], a[ks][1][2], a[ks][1][3], aLm[1] + ko);
            #pragma unroll
            for (int p = 0; p < 4; p++)
                LDSM4(bf[ks][p][0], bf[ks][p][1], bf[ks][p][2], bf[ks][p][3], bLm[p] + ko);
        }
        // --- then all 32 MMAs ---
        #pragma unroll
        for (int ks = 0; ks < 2; ks++) {
            #pragma unroll
            for (int t = 0; t < 8; t++) {
                uint32_t b0 = bf[ks][t >> 1][(t & 1) * 2 + 0];
                uint32_t b1 = bf[ks][t >> 1][(t & 1) * 2 + 1];
                #pragma unroll
                for (int i = 0; i < 2; i++) mma16(acc[i][t], a[ks][i], b0, b1);
            }
        }
    }
    #undef LDGA
    #undef STSA
    #undef CPB

    // ---- epilogue ----
    #pragma unroll
    for (int i = 0; i < 2; i++) {
        #pragma unroll
        for (int rh = 0; rh < 2; rh++) {
            float s = 0.f;
            #pragma unroll
            for (int t = 0; t < 8; t++) {
                int n0 = wn * 64 + t * 8 + 2 * lt;
                float c0 = acc[i][t][rh * 2 + 0] + rp_s[n0];
                float c1 = acc[i][t][rh * 2 + 1] + rp_s[n0 + 1];
                s += c0 * c0 + c1 * c1;
            }
            s += __shfl_xor_sync(0xffffffffu, s, 1);
            s += __shfl_xor_sync(0xffffffffu, s, 2);
            if (lt == 0) sqp[wm * 32 + i * 16 + rh * 8 + lg][wn] = s;
        }
    }
    __syncthreads();
    if (tid < BM) {
        float sq = sqp[tid][0] + sqp[tid][1] + sqp[tid][2] + sqp[tid][3];
        invb[tid] = 1.0f / fmaxf(sqrtf(sq), 1e-12f);
    }
    __syncthreads();

    #pragma unroll
    for (int i = 0; i < 2; i++) {
        #pragma unroll
        for (int rh = 0; rh < 2; rh++) {
            int row = wm * 32 + i * 16 + rh * 8 + lg;
            float inv = invb[row];
            float s = 0.f;
            #pragma unroll
            for (int t = 0; t < 8; t++) {
                int n0 = wn * 64 + t * 8 + 2 * lt;
                float t0 = (acc[i][t][rh * 2 + 0] + rp_s[n0])     * inv;
                float t1 = (acc[i][t][rh * 2 + 1] + rp_s[n0 + 1]) * inv;
                s += fabsf(hn_s[n0] - t0) + fabsf(hn_s[n0 + 1] - t1);
            }
            s += __shfl_xor_sync(0xffffffffu, s, 1);
            s += __shfl_xor_sync(0xffffffffu, s, 2);
            if (lt == 0) spp[row][wn] = s;
        }
    }
    __syncthreads();
    if (tid < BM)
        out[b * NNEG + tile0 + tid] =
            12.0f - (spp[tid][0] + spp[tid][1] + spp[tid][2] + spp[tid][3]);
}

// ---------------------------------------------------------------------------
extern "C" void kernel_launch(void* const* d_in, const int* in_sizes, int n_in,
                              void* d_out, int out_size)
{
    const int*   head = (const int*)  d_in[0];
    const int*   tail = (const int*)  d_in[1];
    const int*   rel  = (const int*)  d_in[2];
    const float* ent  = (const float*)d_in[3];
    const float* remb = (const float*)d_in[4];
    const float* W    = (const float*)d_in[5];
    const float* bfc  = (const float*)d_in[6];
    float* out = (float*)d_out;

    cudaFuncSetAttribute(k_main, cudaFuncAttributeMaxDynamicSharedMemorySize, SMEM_MAIN);

    k_transW<<<dim3(16, 8), dim3(32, 32)>>>(W);
    k_prep<<<NB / 4, 256>>>(head, rel, ent, remb, bfc);
    k_main<<<dim3(NNEG / BM, NB), 512, SMEM_MAIN>>>(tail, ent, out);
}